// round 13
// baseline (speedup 1.0000x reference)
#include <cuda_runtime.h>
#include <cuda_bf16.h>
#include <cstdint>

// Problem constants
#define B_ 4
#define S_ 2048
#define E_ 1024
#define H_ 16
#define D_ 64

// Scratch (device globals; no allocation allowed)
__device__ float g_Q[(size_t)B_ * H_ * S_ * D_];
__device__ float g_K[(size_t)B_ * H_ * S_ * D_];
__device__ float g_V[(size_t)B_ * H_ * S_ * D_];
__device__ float g_AO[(size_t)B_ * S_ * E_];   // fragment-major A for O-proj
__device__ float g_X[(size_t)B_ * S_ * E_];    // fragment-major A (tf32)
__device__ float g_WQ[(size_t)E_ * E_];        // fragment-major B (tf32)
__device__ float g_WK[(size_t)E_ * E_];
__device__ float g_WV[(size_t)E_ * E_];
__device__ float g_WO[(size_t)E_ * E_];

// Fragment-major layouts (K = E_ = 1024, so 128 k0-blocks):
//  A: float idx = (M16*128 + K0)*128 + lane*4 + word
//     lane = (m&7)*4 + (k&3), word = ((m>>3)&1) + 2*((k>>2)&1)
//  B: float idx = (N8*128 + K0)*64 + lane*2 + word
//     lane = (n&7)*4 + (k&3), word = (k>>2)&1

__device__ __forceinline__ float to_tf32(float x) {
    uint32_t u;
    asm("cvt.rna.tf32.f32 %0, %1;" : "=r"(u) : "f"(x));
    return __uint_as_float(u);
}

__device__ __forceinline__ void mma_tf32(float* c, const uint32_t* a, const uint32_t* b) {
    asm volatile(
        "mma.sync.aligned.m16n8k8.row.col.f32.tf32.tf32.f32 "
        "{%0,%1,%2,%3}, {%4,%5,%6,%7}, {%8,%9}, {%0,%1,%2,%3};"
        : "+f"(c[0]), "+f"(c[1]), "+f"(c[2]), "+f"(c[3])
        : "r"(a[0]), "r"(a[1]), "r"(a[2]), "r"(a[3]), "r"(b[0]), "r"(b[1]));
}

__device__ __forceinline__ void cp16(uint32_t dst, const void* src) {
    asm volatile("cp.async.cg.shared.global [%0], [%1], 16;"
                 :: "r"(dst), "l"(src) : "memory");
}
#define CP_COMMIT() asm volatile("cp.async.commit_group;" ::: "memory")
#define CP_WAIT1()  asm volatile("cp.async.wait_group 1;" ::: "memory")

// ---------------------------------------------------------------------------
// Input conversion: tf32-round AND relayout into fragment-major order.
// X: 2,097,152 units (16B, 4 gathers + STG.128 each).
// W: 4 x 524,288 units (8B, 2 gathers + STG.64 each).
// ---------------------------------------------------------------------------
#define NXU 2097152
#define NWU 524288

__global__ __launch_bounds__(256) void cvt_inputs(
    const float* __restrict__ x,
    const float* __restrict__ wq, const float* __restrict__ wk,
    const float* __restrict__ wv, const float* __restrict__ wo,
    float* __restrict__ xt,
    float* __restrict__ wqt, float* __restrict__ wkt,
    float* __restrict__ wvt, float* __restrict__ wot) {
    int t = blockIdx.x * 256 + threadIdx.x;
    if (t < NXU) {
        // unit id = (M*128 + K0)*32 + lane
        int lane = t & 31;
        int K0 = (t >> 5) & 127;
        int M = t >> 12;
        int m7 = lane >> 2, k3 = lane & 3;
        const float* xr = x + (size_t)(M * 16 + m7) * E_ + K0 * 8 + k3;
        float w0 = to_tf32(xr[0]);
        float w1 = to_tf32(xr[8 * E_]);
        float w2 = to_tf32(xr[4]);
        float w3 = to_tf32(xr[8 * E_ + 4]);
        *(float4*)(xt + (size_t)t * 4) = make_float4(w0, w1, w2, w3);
        return;
    }
    t -= NXU;
    int mat = t >> 19;
    int id = t & (NWU - 1);
    const float* s;
    float* d;
    if (mat == 0)      { s = wq; d = wqt; }
    else if (mat == 1) { s = wk; d = wkt; }
    else if (mat == 2) { s = wv; d = wvt; }
    else               { s = wo; d = wot; }
    int lane = id & 31;
    int K0 = (id >> 5) & 127;
    int N8 = id >> 12;
    int n7 = lane >> 2, k3 = lane & 3;
    const float* wr = s + (size_t)(N8 * 8 + n7) * E_ + K0 * 8 + k3;
    float w0 = to_tf32(wr[0]);
    float w1 = to_tf32(wr[4]);
    *(float2*)(d + (size_t)id * 2) = make_float2(w0, w1);
}

// ---------------------------------------------------------------------------
// TF32 tensor-core GEMM on fragment-major operands.
// Tile 128x128, K-chunk 32, 3-stage cp.async (96 KB dynamic smem), 256 thr,
// warp grid 2x4, warp tile 64x32. Fragment loads are LDS.128/LDS.64 at
// lane-linear addresses — no swizzle, no address math in the hot loop.
// blockIdx.z selects (W, C). SPLIT=true writes Q/K/V [B,H,S,D] (tf32).
// ---------------------------------------------------------------------------
#define GEMM_SMEM (3 * 16384 * 2)   // 98304 B

template <bool SPLIT>
__global__ __launch_bounds__(256, 2) void gemm_tf32(
    const float* __restrict__ A,
    const float* __restrict__ W0, const float* __restrict__ W1,
    const float* __restrict__ W2,
    float* __restrict__ C0, float* __restrict__ C1, float* __restrict__ C2) {
    extern __shared__ float dsm[];
    // A stage s: floats [s*4096, +4096); B stage s: floats [12288 + s*4096, +4096)

    const float* W = W0;
    float* C = C0;
    if (blockIdx.z == 1) { W = W1; C = C1; }
    else if (blockIdx.z == 2) { W = W2; C = C2; }

    const int tid = threadIdx.x;
    const int bm = blockIdx.y * 128, bn = blockIdx.x * 128;
    const int wid = tid >> 5, lane = tid & 31;
    const int lr = lane >> 2, lc = lane & 3;
    const int mbase = (wid & 1) * 4;    // m-block16 base within tile (of 8)
    const int nbase = (wid >> 1) * 4;   // n-block8 base within tile (of 16)

    const uint32_t sa = (uint32_t)__cvta_generic_to_shared(dsm);
    const uint32_t sb = sa + 49152u;

    // cp.async unit decode (A): u in [0,1024): block=u>>5 (mblk=block>>2,
    // k0blk=block&3), ln=u&31. Global float = ((Mb*128+K0g)*128 + ln*4).
    // (B): block=u>>4 is wrong-size; B: u>>4 gives 64 blocks (nblk=blk>>2,
    // k0blk=blk&3), pair=u&15. Global float = ((N8*128+K0g)*64 + pair*4).
    const int Mtile = bm >> 4;   // first m-block16
    const int Ntile = bn >> 3;   // first n-block8

    float acc[4][4][4];
#pragma unroll
    for (int mt = 0; mt < 4; mt++)
#pragma unroll
        for (int nt = 0; nt < 4; nt++)
#pragma unroll
            for (int i = 0; i < 4; i++) acc[mt][nt][i] = 0.f;

    const int NCHUNK = E_ / 32;  // 32

    // cp.async issue helper (4 A units + 4 B units per thread per chunk)
    auto issue_chunk = [&](int c, uint32_t st) {
        const int K0c = c * 4;  // first k0-block of chunk
#pragma unroll
        for (int i = 0; i < 4; i++) {
            int u = tid + i * 256;
            // A unit
            int blkA = u >> 5, lnA = u & 31;
            int MbA = Mtile + (blkA >> 2);
            int K0A = K0c + (blkA & 3);
            cp16(sa + st + (uint32_t)u * 16,
                 A + ((size_t)(MbA * 128 + K0A) * 128 + lnA * 4));
            // B unit
            int blkB = u >> 4, prB = u & 15;
            int N8B = Ntile + (blkB >> 2);
            int K0B = K0c + (blkB & 3);
            cp16(sb + st + (uint32_t)u * 16,
                 W + ((size_t)(N8B * 128 + K0B) * 64 + prB * 4));
        }
    };

    issue_chunk(0, 0u);
    CP_COMMIT();
    issue_chunk(1, 16384u);
    CP_COMMIT();

#pragma unroll 1
    for (int c = 0; c < NCHUNK; c++) {
        CP_WAIT1();
        __syncthreads();

        if (c + 2 < NCHUNK) issue_chunk(c + 2, (uint32_t)((c + 2) % 3) * 16384u);
        CP_COMMIT();

        const uint4* Ab = (const uint4*)(dsm + (c % 3) * 4096);
        const uint2* Bb = (const uint2*)(dsm + 12288 + (c % 3) * 4096);
#pragma unroll
        for (int k0 = 0; k0 < 4; k0++) {
            uint4 af[4];
            uint2 bf[4];
#pragma unroll
            for (int mt = 0; mt < 4; mt++)
                af[mt] = Ab[((mbase + mt) * 4 + k0) * 32 + lane];
#pragma unroll
            for (int nt = 0; nt < 4; nt++)
                bf[nt] = Bb[((nbase + nt) * 4 + k0) * 32 + lane];
#pragma unroll
            for (int mt = 0; mt < 4; mt++)
#pragma unroll
                for (int nt = 0; nt < 4; nt++)
                    mma_tf32(acc[mt][nt], (const uint32_t*)&af[mt],
                             (const uint32_t*)&bf[nt]);
        }
    }

    // Epilogue: standard row-major outputs (Q/K/V split, or final out)
#pragma unroll
    for (int mt = 0; mt < 4; mt++) {
#pragma unroll
        for (int nt = 0; nt < 4; nt++) {
            int row = bm + ((wid & 1) * 4 + mt) * 16 + lr;
            int col = bn + ((wid >> 1) * 4 + nt) * 8 + lc * 2;
#pragma unroll
            for (int half = 0; half < 2; half++) {
                int m = row + half * 8;
                float v0 = acc[mt][nt][half * 2], v1 = acc[mt][nt][half * 2 + 1];
                if (!SPLIT) {
                    *(float2*)(C + (size_t)m * E_ + col) = make_float2(v0, v1);
                } else {
                    int b = m >> 11, sq = m & 2047;
                    int h = col >> 6, d = col & 63;
                    *(float2*)(C + ((((size_t)b * H_ + h) * S_ + sq) * D_ + d)) =
                        make_float2(to_tf32(v0), to_tf32(v1));
                }
            }
        }
    }
}

// ---------------------------------------------------------------------------
// Tensor-core flash attention (tf32 mma, fp32 softmax).
// Q/K/V tf32-rounded row-major. AO written FRAGMENT-MAJOR (tf32) for O-proj,
// via the same intra-quad shuffle pattern as the P relayout.
// ---------------------------------------------------------------------------
__global__ __launch_bounds__(256) void flash_tc(const float* __restrict__ Q,
                                                const float* __restrict__ K,
                                                const float* __restrict__ V,
                                                const int* __restrict__ amask,
                                                float* __restrict__ out) {
    extern __shared__ float smf[];
    float* Qs = smf;                   // 128 x 68
    float* Ks = Qs + 128 * 68;         // 64 x 68
    float* Vs = Ks + 64 * 68;          // 64 x 72
    __shared__ unsigned mkb[2];

    const int tid = threadIdx.x;
    const int qt = blockIdx.x;
    const int bh = blockIdx.y;
    const int b = bh >> 4, h = bh & 15;
    const int qbase = qt * 128;

    const int lane = tid & 31, wid = tid >> 5;
    const int lr = lane >> 2, lc = lane & 3;
    const int wb = wid * 16;

    {
        const float* Qb = Q + ((size_t)bh * S_ + qbase) * D_;
        for (int e = tid; e < 2048; e += 256) {
            int r = e >> 4, c4 = e & 15;
            float4 v = ((const float4*)Qb)[e];
            *(float4*)&Qs[r * 68 + c4 * 4] =
                make_float4(v.x * 0.125f, v.y * 0.125f, v.z * 0.125f, v.w * 0.125f);
        }
    }

    const int grow0 = qbase + wb + lr;
    const int grow1 = grow0 + 8;

    float oacc[8][4];
#pragma unroll
    for (int nt = 0; nt < 8; nt++)
#pragma unroll
        for (int j = 0; j < 4; j++) oacc[nt][j] = 0.f;

    float mlo = -1e30f, mhi = -1e30f, llo = 0.f, lhi = 0.f;

    const int ntiles = 2 * qt + 2;
    for (int kt = 0; kt < ntiles; kt++) {
        __syncthreads();

        const float* Kb = K + ((size_t)bh * S_ + kt * 64) * D_;
        const float* Vb = V + ((size_t)bh * S_ + kt * 64) * D_;
        for (int e = tid; e < 1024; e += 256) {
            int r = e >> 4, c4 = e & 15;
            *(float4*)&Ks[r * 68 + c4 * 4] = ((const float4*)Kb)[e];
            *(float4*)&Vs[r * 72 + c4 * 4] = ((const float4*)Vb)[e];
        }
        if (tid < 64) {
            int m = amask[b * S_ + kt * 64 + tid];
            unsigned bal = __ballot_sync(0xffffffffu, m != 0);
            if ((tid & 31) == 0) mkb[tid >> 5] = bal;
        }
        __syncthreads();

        float sacc[8][4];
#pragma unroll
        for (int nt = 0; nt < 8; nt++)
#pragma unroll
            for (int j = 0; j < 4; j++) sacc[nt][j] = 0.f;

#pragma unroll
        for (int ks = 0; ks < 8; ks++) {
            int k0 = ks * 8;
            uint32_t a[4];
            a[0] = __float_as_uint(Qs[(wb + lr) * 68 + k0 + lc]);
            a[1] = __float_as_uint(Qs[(wb + lr + 8) * 68 + k0 + lc]);
            a[2] = __float_as_uint(Qs[(wb + lr) * 68 + k0 + 4 + lc]);
            a[3] = __float_as_uint(Qs[(wb + lr + 8) * 68 + k0 + 4 + lc]);
#pragma unroll
            for (int nt = 0; nt < 8; nt++) {
                uint32_t bb[2];
                bb[0] = __float_as_uint(Ks[(nt * 8 + lr) * 68 + k0 + lc]);
                bb[1] = __float_as_uint(Ks[(nt * 8 + lr) * 68 + k0 + 4 + lc]);
                mma_tf32(sacc[nt], a, bb);
            }
        }

        unsigned mb0 = mkb[0], mb1 = mkb[1];
        bool diag = (kt >= 2 * qt);
        bool pad = (mb0 & mb1) != 0xffffffffu;
        if (diag || pad) {
#pragma unroll
            for (int nt = 0; nt < 8; nt++) {
#pragma unroll
                for (int j = 0; j < 4; j++) {
                    int colL = nt * 8 + 2 * lc + (j & 1);
                    int gcol = kt * 64 + colL;
                    int grow = (j < 2) ? grow0 : grow1;
                    unsigned bit = ((colL < 32 ? mb0 : mb1) >> (colL & 31)) & 1u;
                    if (!bit || gcol > grow) sacc[nt][j] = -1e30f;
                }
            }
        }

        float tlo = -1e30f, thi = -1e30f;
#pragma unroll
        for (int nt = 0; nt < 8; nt++) {
            tlo = fmaxf(tlo, fmaxf(sacc[nt][0], sacc[nt][1]));
            thi = fmaxf(thi, fmaxf(sacc[nt][2], sacc[nt][3]));
        }
        tlo = fmaxf(tlo, __shfl_xor_sync(0xffffffffu, tlo, 1));
        tlo = fmaxf(tlo, __shfl_xor_sync(0xffffffffu, tlo, 2));
        thi = fmaxf(thi, __shfl_xor_sync(0xffffffffu, thi, 1));
        thi = fmaxf(thi, __shfl_xor_sync(0xffffffffu, thi, 2));

        float nmlo = fmaxf(mlo, tlo), nmhi = fmaxf(mhi, thi);
        float alo = __expf(mlo - nmlo), ahi = __expf(mhi - nmhi);
        mlo = nmlo; mhi = nmhi;

        float slo = 0.f, shi = 0.f;
#pragma unroll
        for (int nt = 0; nt < 8; nt++) {
            float p0 = to_tf32(__expf(sacc[nt][0] - nmlo));
            float p1 = to_tf32(__expf(sacc[nt][1] - nmlo));
            float p2 = to_tf32(__expf(sacc[nt][2] - nmhi));
            float p3 = to_tf32(__expf(sacc[nt][3] - nmhi));
            sacc[nt][0] = p0; sacc[nt][1] = p1;
            sacc[nt][2] = p2; sacc[nt][3] = p3;
            slo += p0 + p1; shi += p2 + p3;
        }
        slo += __shfl_xor_sync(0xffffffffu, slo, 1);
        slo += __shfl_xor_sync(0xffffffffu, slo, 2);
        shi += __shfl_xor_sync(0xffffffffu, shi, 1);
        shi += __shfl_xor_sync(0xffffffffu, shi, 2);
        llo = llo * alo + slo;
        lhi = lhi * ahi + shi;

#pragma unroll
        for (int nt = 0; nt < 8; nt++) {
            oacc[nt][0] *= alo; oacc[nt][1] *= alo;
            oacc[nt][2] *= ahi; oacc[nt][3] *= ahi;
        }

        const int src0 = (lane & 28) | (lc >> 1);
        const int src1 = src0 + 2;
#pragma unroll
        for (int ks = 0; ks < 8; ks++) {
            float p0 = sacc[ks][0], p1 = sacc[ks][1];
            float p2 = sacc[ks][2], p3 = sacc[ks][3];
            float u0 = __shfl_sync(0xffffffffu, p0, src0);
            float u1 = __shfl_sync(0xffffffffu, p1, src0);
            float u2 = __shfl_sync(0xffffffffu, p2, src0);
            float u3 = __shfl_sync(0xffffffffu, p3, src0);
            float v0 = __shfl_sync(0xffffffffu, p0, src1);
            float v1 = __shfl_sync(0xffffffffu, p1, src1);
            float v2 = __shfl_sync(0xffffffffu, p2, src1);
            float v3 = __shfl_sync(0xffffffffu, p3, src1);
            uint32_t a[4];
            a[0] = __float_as_uint((lc & 1) ? u1 : u0);
            a[1] = __float_as_uint((lc & 1) ? u3 : u2);
            a[2] = __float_as_uint((lc & 1) ? v1 : v0);
            a[3] = __float_as_uint((lc & 1) ? v3 : v2);
#pragma unroll
            for (int nt = 0; nt < 8; nt++) {
                uint32_t bb[2];
                bb[0] = __float_as_uint(Vs[(ks * 8 + lc) * 72 + nt * 8 + lr]);
                bb[1] = __float_as_uint(Vs[(ks * 8 + 4 + lc) * 72 + nt * 8 + lr]);
                mma_tf32(oacc[nt], a, bb);
            }
        }
    }

    // Epilogue: write AO in FRAGMENT-MAJOR layout (tf32-rounded).
    // M block = (b*S + qbase + wb)/16; K0 = h*8 + nt.
    const float il0 = 1.f / llo, il1 = 1.f / lhi;
    const int M = (b * S_ + qbase + wb) >> 4;
    const int src0 = (lane & 28) | (lc >> 1);
    const int src1 = src0 + 2;
#pragma unroll
    for (int nt = 0; nt < 8; nt++) {
        float c0 = oacc[nt][0] * il0, c1 = oacc[nt][1] * il0;
        float c2 = oacc[nt][2] * il1, c3 = oacc[nt][3] * il1;
        float u0 = __shfl_sync(0xffffffffu, c0, src0);
        float u1 = __shfl_sync(0xffffffffu, c1, src0);
        float u2 = __shfl_sync(0xffffffffu, c2, src0);
        float u3 = __shfl_sync(0xffffffffu, c3, src0);
        float v0 = __shfl_sync(0xffffffffu, c0, src1);
        float v1 = __shfl_sync(0xffffffffu, c1, src1);
        float v2 = __shfl_sync(0xffffffffu, c2, src1);
        float v3 = __shfl_sync(0xffffffffu, c3, src1);
        float w0 = to_tf32((lc & 1) ? u1 : u0);   // (lr,   lc)
        float w1 = to_tf32((lc & 1) ? u3 : u2);   // (lr+8, lc)
        float w2 = to_tf32((lc & 1) ? v1 : v0);   // (lr,   lc+4)
        float w3 = to_tf32((lc & 1) ? v3 : v2);   // (lr+8, lc+4)
        int K0 = h * 8 + nt;
        *(float4*)(out + ((size_t)(M * 128 + K0) * 128 + lane * 4)) =
            make_float4(w0, w1, w2, w3);
    }
}

// ---------------------------------------------------------------------------
// Launch
// ---------------------------------------------------------------------------
extern "C" void kernel_launch(void* const* d_in, const int* in_sizes, int n_in,
                              void* d_out, int out_size) {
    const float* x     = (const float*)d_in[0];
    const int*   amask = (const int*)d_in[1];
    const float* wq    = (const float*)d_in[2];
    const float* wk    = (const float*)d_in[3];
    const float* wv    = (const float*)d_in[4];
    const float* wo    = (const float*)d_in[5];
    float* out = (float*)d_out;

    float *qp, *kp, *vp, *aop, *xt, *wqt, *wkt, *wvt, *wot;
    cudaGetSymbolAddress((void**)&qp, g_Q);
    cudaGetSymbolAddress((void**)&kp, g_K);
    cudaGetSymbolAddress((void**)&vp, g_V);
    cudaGetSymbolAddress((void**)&aop, g_AO);
    cudaGetSymbolAddress((void**)&xt, g_X);
    cudaGetSymbolAddress((void**)&wqt, g_WQ);
    cudaGetSymbolAddress((void**)&wkt, g_WK);
    cudaGetSymbolAddress((void**)&wvt, g_WV);
    cudaGetSymbolAddress((void**)&wot, g_WO);

    // tf32 rounding + fragment-major relayout of all GEMM inputs
    const int NT = NXU + 4 * NWU;  // 4,194,304 threads
    cvt_inputs<<<NT / 256, 256>>>(x, wq, wk, wv, wo, xt, wqt, wkt, wvt, wot);

    cudaFuncSetAttribute(gemm_tf32<true>,
                         cudaFuncAttributeMaxDynamicSharedMemorySize, GEMM_SMEM);
    cudaFuncSetAttribute(gemm_tf32<false>,
                         cudaFuncAttributeMaxDynamicSharedMemorySize, GEMM_SMEM);

    // Fused Q/K/V projections
    gemm_tf32<true><<<dim3(E_ / 128, (B_ * S_) / 128, 3), 256, GEMM_SMEM>>>(
        xt, wqt, wkt, wvt, qp, kp, vp);

    // Tensor-core flash attention (writes AO fragment-major)
    size_t fa_smem = (128 * 68 + 64 * 68 + 64 * 72) * sizeof(float);
    cudaFuncSetAttribute(flash_tc, cudaFuncAttributeMaxDynamicSharedMemorySize,
                         (int)fa_smem);
    flash_tc<<<dim3(S_ / 128, B_ * H_), 256, fa_smem>>>(qp, kp, vp, amask, aop);

    // Output projection
    gemm_tf32<false><<<dim3(E_ / 128, (B_ * S_) / 128, 1), 256, GEMM_SMEM>>>(
        aop, wot, wot, wot, out, out, out);
}

// round 14
// speedup vs baseline: 1.0994x; 1.0994x over previous
#include <cuda_runtime.h>
#include <cuda_bf16.h>
#include <cstdint>

// Problem constants
#define B_ 4
#define S_ 2048
#define E_ 1024
#define H_ 16
#define D_ 64

// Scratch (device globals; no allocation allowed)
__device__ float g_Q[(size_t)B_ * H_ * S_ * D_];
__device__ float g_K[(size_t)B_ * H_ * S_ * D_];
__device__ float g_V[(size_t)B_ * H_ * S_ * D_];
__device__ float g_AO[(size_t)B_ * S_ * E_];
__device__ float g_X[(size_t)B_ * S_ * E_];    // tf32-rounded x
__device__ float g_WQ[(size_t)E_ * E_];        // tf32-rounded weights
__device__ float g_WK[(size_t)E_ * E_];
__device__ float g_WV[(size_t)E_ * E_];
__device__ float g_WO[(size_t)E_ * E_];

__device__ __forceinline__ float to_tf32(float x) {
    uint32_t u;
    asm("cvt.rna.tf32.f32 %0, %1;" : "=r"(u) : "f"(x));
    return __uint_as_float(u);
}

__device__ __forceinline__ float4 cvt4(float4 v) {
    return make_float4(to_tf32(v.x), to_tf32(v.y), to_tf32(v.z), to_tf32(v.w));
}

__device__ __forceinline__ void mma_tf32(float* c, const uint32_t* a, const uint32_t* b) {
    asm volatile(
        "mma.sync.aligned.m16n8k8.row.col.f32.tf32.tf32.f32 "
        "{%0,%1,%2,%3}, {%4,%5,%6,%7}, {%8,%9}, {%0,%1,%2,%3};"
        : "+f"(c[0]), "+f"(c[1]), "+f"(c[2]), "+f"(c[3])
        : "r"(a[0]), "r"(a[1]), "r"(a[2]), "r"(a[3]), "r"(b[0]), "r"(b[1]));
}

__device__ __forceinline__ void cp16(uint32_t dst, const void* src) {
    asm volatile("cp.async.cg.shared.global [%0], [%1], 16;"
                 :: "r"(dst), "l"(src) : "memory");
}
#define CP_COMMIT() asm volatile("cp.async.commit_group;" ::: "memory")
#define CP_WAIT1()  asm volatile("cp.async.wait_group 1;" ::: "memory")

// Smem tile [128 rows][32 floats]: col4-group XOR (row & 7). Conflict-free for
// both 16B cp.async stores and per-quad fragment LDS.
__device__ __forceinline__ int SWZ32(int r, int c) {
    return r * 32 + ((((c) >> 2) ^ (r & 7)) << 2) + ((c) & 3);
}

// ---------------------------------------------------------------------------
// Input conversion: round x and the 4 weight matrices to tf32 once (linear).
// ---------------------------------------------------------------------------
__global__ __launch_bounds__(256) void cvt_inputs(
    const float* __restrict__ x,
    const float* __restrict__ wq, const float* __restrict__ wk,
    const float* __restrict__ wv, const float* __restrict__ wo,
    float* __restrict__ xt,
    float* __restrict__ wqt, float* __restrict__ wkt,
    float* __restrict__ wvt, float* __restrict__ wot) {
    const int NX = (B_ * S_ * E_) / 4;   // 2,097,152
    const int NW = (E_ * E_) / 4;        // 262,144
    int i = blockIdx.x * 256 + threadIdx.x;
    if (i < NX) {
        ((float4*)xt)[i] = cvt4(((const float4*)x)[i]);
        return;
    }
    i -= NX;
    const float* s;
    float* d;
    if (i < NW)          { s = wq; d = wqt; }
    else if (i < 2 * NW) { s = wk; d = wkt; i -= NW; }
    else if (i < 3 * NW) { s = wv; d = wvt; i -= 2 * NW; }
    else                 { s = wo; d = wot; i -= 3 * NW; }
    ((float4*)d)[i] = cvt4(((const float4*)s)[i]);
}

// ---------------------------------------------------------------------------
// TF32 tensor-core GEMM: C[M,N] = A[M,K] * W[N,K]^T  (R10 formulation)
// K-chunk = 32 (one 128B atom row), 3-stage cp.async, one wait+sync / 64 MMAs.
// Tile 128x128, 256 threads, warp grid 2x4, warp tile 64x32.
// ---------------------------------------------------------------------------
#define GEMM_SMEM (3 * 16384 * 2)   // 98304 B

template <bool SPLIT>
__global__ __launch_bounds__(256, 2) void gemm_tf32(
    const float* __restrict__ A,
    const float* __restrict__ W0, const float* __restrict__ W1,
    const float* __restrict__ W2,
    float* __restrict__ C0, float* __restrict__ C1, float* __restrict__ C2) {
    const int K = E_;
    extern __shared__ float dsm[];

    const float* W = W0;
    float* C = C0;
    if (blockIdx.z == 1) { W = W1; C = C1; }
    else if (blockIdx.z == 2) { W = W2; C = C2; }

    const int tid = threadIdx.x;
    const int bm = blockIdx.y * 128, bn = blockIdx.x * 128;
    const int wid = tid >> 5, lane = tid & 31;
    const int lr = lane >> 2, lc = lane & 3;
    const int mb = (wid & 1) * 64;
    const int nb = (wid >> 1) * 32;

    const int r0 = tid >> 3;
    const int cg = tid & 7;
    const uint32_t aoff = (uint32_t)(r0 * 128 + ((cg ^ (r0 & 7)) * 16));

    const uint32_t sa = (uint32_t)__cvta_generic_to_shared(dsm);
    const uint32_t sb = sa + 49152u;

    const float* Ap = A + (size_t)(bm + r0) * K + cg * 4;
    const float* Wp = W + (size_t)(bn + r0) * K + cg * 4;

    float acc[4][4][4];
#pragma unroll
    for (int mt = 0; mt < 4; mt++)
#pragma unroll
        for (int nt = 0; nt < 4; nt++)
#pragma unroll
            for (int i = 0; i < 4; i++) acc[mt][nt][i] = 0.f;

    const int NCHUNK = K / 32;  // 32

#pragma unroll
    for (int c = 0; c < 2; c++) {
        const uint32_t st = (uint32_t)c * 16384u;
        const int kc = c * 32;
#pragma unroll
        for (int i = 0; i < 4; i++) {
            cp16(sa + st + aoff + i * 4096u, Ap + (size_t)(i * 32) * K + kc);
            cp16(sb + st + aoff + i * 4096u, Wp + (size_t)(i * 32) * K + kc);
        }
        CP_COMMIT();
    }

#pragma unroll 1
    for (int c = 0; c < NCHUNK; c++) {
        CP_WAIT1();
        __syncthreads();

        if (c + 2 < NCHUNK) {
            const uint32_t st = (uint32_t)((c + 2) % 3) * 16384u;
            const int kc = (c + 2) * 32;
#pragma unroll
            for (int i = 0; i < 4; i++) {
                cp16(sa + st + aoff + i * 4096u, Ap + (size_t)(i * 32) * K + kc);
                cp16(sb + st + aoff + i * 4096u, Wp + (size_t)(i * 32) * K + kc);
            }
        }
        CP_COMMIT();

        const float* Asb = dsm + (c % 3) * 4096;
        const float* Bsb = dsm + 12288 + (c % 3) * 4096;
#pragma unroll
        for (int k0 = 0; k0 < 32; k0 += 8) {
            uint32_t af[4][4], bf[4][2];
#pragma unroll
            for (int mt = 0; mt < 4; mt++) {
                int m = mb + mt * 16 + lr;
                af[mt][0] = __float_as_uint(Asb[SWZ32(m, k0 + lc)]);
                af[mt][1] = __float_as_uint(Asb[SWZ32(m + 8, k0 + lc)]);
                af[mt][2] = __float_as_uint(Asb[SWZ32(m, k0 + 4 + lc)]);
                af[mt][3] = __float_as_uint(Asb[SWZ32(m + 8, k0 + 4 + lc)]);
            }
#pragma unroll
            for (int nt = 0; nt < 4; nt++) {
                int n = nb + nt * 8 + lr;
                bf[nt][0] = __float_as_uint(Bsb[SWZ32(n, k0 + lc)]);
                bf[nt][1] = __float_as_uint(Bsb[SWZ32(n, k0 + 4 + lc)]);
            }
#pragma unroll
            for (int mt = 0; mt < 4; mt++)
#pragma unroll
                for (int nt = 0; nt < 4; nt++)
                    mma_tf32(acc[mt][nt], af[mt], bf[nt]);
        }
    }

#pragma unroll
    for (int mt = 0; mt < 4; mt++) {
#pragma unroll
        for (int nt = 0; nt < 4; nt++) {
            int row = bm + mb + mt * 16 + lr;
            int col = bn + nb + nt * 8 + lc * 2;
#pragma unroll
            for (int half = 0; half < 2; half++) {
                int m = row + half * 8;
                float v0 = acc[mt][nt][half * 2], v1 = acc[mt][nt][half * 2 + 1];
                if (!SPLIT) {
                    *(float2*)(C + (size_t)m * E_ + col) = make_float2(v0, v1);
                } else {
                    int b = m >> 11, sq = m & 2047;
                    int h = col >> 6, d = col & 63;
                    *(float2*)(C + ((((size_t)b * H_ + h) * S_ + sq) * D_ + d)) =
                        make_float2(to_tf32(v0), to_tf32(v1));
                }
            }
        }
    }
}

// ---------------------------------------------------------------------------
// Tensor-core flash attention (tf32 mma, fp32 softmax).
// HEAVY-FIRST grid: bh = blockIdx.x (fast), qt = 15 - blockIdx.y, so the
// 32-tile causal CTAs launch first and the 2-tile ones fill the tail (LPT).
// ---------------------------------------------------------------------------
__global__ __launch_bounds__(256) void flash_tc(const float* __restrict__ Q,
                                                const float* __restrict__ K,
                                                const float* __restrict__ V,
                                                const int* __restrict__ amask,
                                                float* __restrict__ out) {
    extern __shared__ float smf[];
    float* Qs = smf;                   // 128 x 68
    float* Ks = Qs + 128 * 68;         // 64 x 68
    float* Vs = Ks + 64 * 68;          // 64 x 72
    __shared__ unsigned mkb[2];

    const int tid = threadIdx.x;
    const int bh = blockIdx.x;                       // fast dim
    const int qt = (int)(gridDim.y - 1) - (int)blockIdx.y;  // heavy first
    const int b = bh >> 4, h = bh & 15;
    const int qbase = qt * 128;

    const int lane = tid & 31, wid = tid >> 5;
    const int lr = lane >> 2, lc = lane & 3;
    const int wb = wid * 16;

    {
        const float* Qb = Q + ((size_t)bh * S_ + qbase) * D_;
        for (int e = tid; e < 2048; e += 256) {
            int r = e >> 4, c4 = e & 15;
            float4 v = ((const float4*)Qb)[e];
            *(float4*)&Qs[r * 68 + c4 * 4] =
                make_float4(v.x * 0.125f, v.y * 0.125f, v.z * 0.125f, v.w * 0.125f);
        }
    }

    const int grow0 = qbase + wb + lr;
    const int grow1 = grow0 + 8;

    float oacc[8][4];
#pragma unroll
    for (int nt = 0; nt < 8; nt++)
#pragma unroll
        for (int j = 0; j < 4; j++) oacc[nt][j] = 0.f;

    float mlo = -1e30f, mhi = -1e30f, llo = 0.f, lhi = 0.f;

    const int ntiles = 2 * qt + 2;
    for (int kt = 0; kt < ntiles; kt++) {
        __syncthreads();

        const float* Kb = K + ((size_t)bh * S_ + kt * 64) * D_;
        const float* Vb = V + ((size_t)bh * S_ + kt * 64) * D_;
        for (int e = tid; e < 1024; e += 256) {
            int r = e >> 4, c4 = e & 15;
            *(float4*)&Ks[r * 68 + c4 * 4] = ((const float4*)Kb)[e];
            *(float4*)&Vs[r * 72 + c4 * 4] = ((const float4*)Vb)[e];
        }
        if (tid < 64) {
            int m = amask[b * S_ + kt * 64 + tid];
            unsigned bal = __ballot_sync(0xffffffffu, m != 0);
            if ((tid & 31) == 0) mkb[tid >> 5] = bal;
        }
        __syncthreads();

        float sacc[8][4];
#pragma unroll
        for (int nt = 0; nt < 8; nt++)
#pragma unroll
            for (int j = 0; j < 4; j++) sacc[nt][j] = 0.f;

#pragma unroll
        for (int ks = 0; ks < 8; ks++) {
            int k0 = ks * 8;
            uint32_t a[4];
            a[0] = __float_as_uint(Qs[(wb + lr) * 68 + k0 + lc]);
            a[1] = __float_as_uint(Qs[(wb + lr + 8) * 68 + k0 + lc]);
            a[2] = __float_as_uint(Qs[(wb + lr) * 68 + k0 + 4 + lc]);
            a[3] = __float_as_uint(Qs[(wb + lr + 8) * 68 + k0 + 4 + lc]);
#pragma unroll
            for (int nt = 0; nt < 8; nt++) {
                uint32_t bb[2];
                bb[0] = __float_as_uint(Ks[(nt * 8 + lr) * 68 + k0 + lc]);
                bb[1] = __float_as_uint(Ks[(nt * 8 + lr) * 68 + k0 + 4 + lc]);
                mma_tf32(sacc[nt], a, bb);
            }
        }

        unsigned mb0 = mkb[0], mb1 = mkb[1];
        bool diag = (kt >= 2 * qt);
        bool pad = (mb0 & mb1) != 0xffffffffu;
        if (diag || pad) {
#pragma unroll
            for (int nt = 0; nt < 8; nt++) {
#pragma unroll
                for (int j = 0; j < 4; j++) {
                    int colL = nt * 8 + 2 * lc + (j & 1);
                    int gcol = kt * 64 + colL;
                    int grow = (j < 2) ? grow0 : grow1;
                    unsigned bit = ((colL < 32 ? mb0 : mb1) >> (colL & 31)) & 1u;
                    if (!bit || gcol > grow) sacc[nt][j] = -1e30f;
                }
            }
        }

        float tlo = -1e30f, thi = -1e30f;
#pragma unroll
        for (int nt = 0; nt < 8; nt++) {
            tlo = fmaxf(tlo, fmaxf(sacc[nt][0], sacc[nt][1]));
            thi = fmaxf(thi, fmaxf(sacc[nt][2], sacc[nt][3]));
        }
        tlo = fmaxf(tlo, __shfl_xor_sync(0xffffffffu, tlo, 1));
        tlo = fmaxf(tlo, __shfl_xor_sync(0xffffffffu, tlo, 2));
        thi = fmaxf(thi, __shfl_xor_sync(0xffffffffu, thi, 1));
        thi = fmaxf(thi, __shfl_xor_sync(0xffffffffu, thi, 2));

        float nmlo = fmaxf(mlo, tlo), nmhi = fmaxf(mhi, thi);
        float alo = __expf(mlo - nmlo), ahi = __expf(mhi - nmhi);
        mlo = nmlo; mhi = nmhi;

        float slo = 0.f, shi = 0.f;
#pragma unroll
        for (int nt = 0; nt < 8; nt++) {
            float p0 = to_tf32(__expf(sacc[nt][0] - nmlo));
            float p1 = to_tf32(__expf(sacc[nt][1] - nmlo));
            float p2 = to_tf32(__expf(sacc[nt][2] - nmhi));
            float p3 = to_tf32(__expf(sacc[nt][3] - nmhi));
            sacc[nt][0] = p0; sacc[nt][1] = p1;
            sacc[nt][2] = p2; sacc[nt][3] = p3;
            slo += p0 + p1; shi += p2 + p3;
        }
        slo += __shfl_xor_sync(0xffffffffu, slo, 1);
        slo += __shfl_xor_sync(0xffffffffu, slo, 2);
        shi += __shfl_xor_sync(0xffffffffu, shi, 1);
        shi += __shfl_xor_sync(0xffffffffu, shi, 2);
        llo = llo * alo + slo;
        lhi = lhi * ahi + shi;

#pragma unroll
        for (int nt = 0; nt < 8; nt++) {
            oacc[nt][0] *= alo; oacc[nt][1] *= alo;
            oacc[nt][2] *= ahi; oacc[nt][3] *= ahi;
        }

        const int src0 = (lane & 28) | (lc >> 1);
        const int src1 = src0 + 2;
#pragma unroll
        for (int ks = 0; ks < 8; ks++) {
            float p0 = sacc[ks][0], p1 = sacc[ks][1];
            float p2 = sacc[ks][2], p3 = sacc[ks][3];
            float u0 = __shfl_sync(0xffffffffu, p0, src0);
            float u1 = __shfl_sync(0xffffffffu, p1, src0);
            float u2 = __shfl_sync(0xffffffffu, p2, src0);
            float u3 = __shfl_sync(0xffffffffu, p3, src0);
            float v0 = __shfl_sync(0xffffffffu, p0, src1);
            float v1 = __shfl_sync(0xffffffffu, p1, src1);
            float v2 = __shfl_sync(0xffffffffu, p2, src1);
            float v3 = __shfl_sync(0xffffffffu, p3, src1);
            uint32_t a[4];
            a[0] = __float_as_uint((lc & 1) ? u1 : u0);
            a[1] = __float_as_uint((lc & 1) ? u3 : u2);
            a[2] = __float_as_uint((lc & 1) ? v1 : v0);
            a[3] = __float_as_uint((lc & 1) ? v3 : v2);
#pragma unroll
            for (int nt = 0; nt < 8; nt++) {
                uint32_t bb[2];
                bb[0] = __float_as_uint(Vs[(ks * 8 + lc) * 72 + nt * 8 + lr]);
                bb[1] = __float_as_uint(Vs[(ks * 8 + 4 + lc) * 72 + nt * 8 + lr]);
                mma_tf32(oacc[nt], a, bb);
            }
        }
    }

    float il0 = 1.f / llo, il1 = 1.f / lhi;
#pragma unroll
    for (int nt = 0; nt < 8; nt++) {
        int col = nt * 8 + 2 * lc;
        float* p0 = out + ((size_t)b * S_ + grow0) * E_ + h * D_ + col;
        float* p1 = out + ((size_t)b * S_ + grow1) * E_ + h * D_ + col;
        *(float2*)p0 = make_float2(to_tf32(oacc[nt][0] * il0),
                                   to_tf32(oacc[nt][1] * il0));
        *(float2*)p1 = make_float2(to_tf32(oacc[nt][2] * il1),
                                   to_tf32(oacc[nt][3] * il1));
    }
}

// ---------------------------------------------------------------------------
// Launch
// ---------------------------------------------------------------------------
extern "C" void kernel_launch(void* const* d_in, const int* in_sizes, int n_in,
                              void* d_out, int out_size) {
    const float* x     = (const float*)d_in[0];
    const int*   amask = (const int*)d_in[1];
    const float* wq    = (const float*)d_in[2];
    const float* wk    = (const float*)d_in[3];
    const float* wv    = (const float*)d_in[4];
    const float* wo    = (const float*)d_in[5];
    float* out = (float*)d_out;

    float *qp, *kp, *vp, *aop, *xt, *wqt, *wkt, *wvt, *wot;
    cudaGetSymbolAddress((void**)&qp, g_Q);
    cudaGetSymbolAddress((void**)&kp, g_K);
    cudaGetSymbolAddress((void**)&vp, g_V);
    cudaGetSymbolAddress((void**)&aop, g_AO);
    cudaGetSymbolAddress((void**)&xt, g_X);
    cudaGetSymbolAddress((void**)&wqt, g_WQ);
    cudaGetSymbolAddress((void**)&wkt, g_WK);
    cudaGetSymbolAddress((void**)&wvt, g_WV);
    cudaGetSymbolAddress((void**)&wot, g_WO);

    // One-time tf32 rounding of all GEMM inputs
    const int NCVT = (B_ * S_ * E_) / 4 + 4 * (E_ * E_) / 4;  // 3,145,728
    cvt_inputs<<<NCVT / 256, 256>>>(x, wq, wk, wv, wo, xt, wqt, wkt, wvt, wot);

    cudaFuncSetAttribute(gemm_tf32<true>,
                         cudaFuncAttributeMaxDynamicSharedMemorySize, GEMM_SMEM);
    cudaFuncSetAttribute(gemm_tf32<false>,
                         cudaFuncAttributeMaxDynamicSharedMemorySize, GEMM_SMEM);

    // Fused Q/K/V projections
    gemm_tf32<true><<<dim3(E_ / 128, (B_ * S_) / 128, 3), 256, GEMM_SMEM>>>(
        xt, wqt, wkt, wvt, qp, kp, vp);

    // Tensor-core flash attention — heavy-first (LPT) CTA order
    size_t fa_smem = (128 * 68 + 64 * 68 + 64 * 72) * sizeof(float);
    cudaFuncSetAttribute(flash_tc, cudaFuncAttributeMaxDynamicSharedMemorySize,
                         (int)fa_smem);
    flash_tc<<<dim3(B_ * H_, S_ / 128), 256, fa_smem>>>(qp, kp, vp, amask, aop);

    // Output projection
    gemm_tf32<false><<<dim3(E_ / 128, (B_ * S_) / 128, 1), 256, GEMM_SMEM>>>(
        aop, wot, wot, wot, out, out, out);
}

// round 16
// speedup vs baseline: 1.2265x; 1.1156x over previous
#include <cuda_runtime.h>
#include <cuda_bf16.h>
#include <cstdint>

// Problem constants
#define B_ 4
#define S_ 2048
#define E_ 1024
#define H_ 16
#define D_ 64

// Scratch (device globals; no allocation allowed)
__device__ float g_Q[(size_t)B_ * H_ * S_ * D_];
__device__ float g_K[(size_t)B_ * H_ * S_ * D_];
__device__ float g_V[(size_t)B_ * H_ * S_ * D_];
__device__ float g_AO[(size_t)B_ * S_ * E_];
__device__ float g_X[(size_t)B_ * S_ * E_];    // tf32-rounded x
__device__ float g_WQ[(size_t)E_ * E_];        // tf32-rounded weights
__device__ float g_WK[(size_t)E_ * E_];
__device__ float g_WV[(size_t)E_ * E_];
__device__ float g_WO[(size_t)E_ * E_];

__device__ __forceinline__ float to_tf32(float x) {
    uint32_t u;
    asm("cvt.rna.tf32.f32 %0, %1;" : "=r"(u) : "f"(x));
    return __uint_as_float(u);
}

__device__ __forceinline__ float4 cvt4(float4 v) {
    return make_float4(to_tf32(v.x), to_tf32(v.y), to_tf32(v.z), to_tf32(v.w));
}

__device__ __forceinline__ void mma_tf32(float* c, const uint32_t* a, const uint32_t* b) {
    asm volatile(
        "mma.sync.aligned.m16n8k8.row.col.f32.tf32.tf32.f32 "
        "{%0,%1,%2,%3}, {%4,%5,%6,%7}, {%8,%9}, {%0,%1,%2,%3};"
        : "+f"(c[0]), "+f"(c[1]), "+f"(c[2]), "+f"(c[3])
        : "r"(a[0]), "r"(a[1]), "r"(a[2]), "r"(a[3]), "r"(b[0]), "r"(b[1]));
}

__device__ __forceinline__ void cp16(uint32_t dst, const void* src) {
    asm volatile("cp.async.cg.shared.global [%0], [%1], 16;"
                 :: "r"(dst), "l"(src) : "memory");
}
#define CP_COMMIT() asm volatile("cp.async.commit_group;" ::: "memory")
#define CP_WAIT1()  asm volatile("cp.async.wait_group 1;" ::: "memory")
#define CP_WAIT0()  asm volatile("cp.async.wait_group 0;" ::: "memory")

// Smem tile [128 rows][32 floats]: col4-group XOR (row & 7). Conflict-free for
// both 16B cp.async stores and per-quad fragment LDS.
__device__ __forceinline__ int SWZ32(int r, int c) {
    return r * 32 + ((((c) >> 2) ^ (r & 7)) << 2) + ((c) & 3);
}

// ---------------------------------------------------------------------------
// Input conversion: round x and the 4 weight matrices to tf32 once (linear).
// ---------------------------------------------------------------------------
__global__ __launch_bounds__(256) void cvt_inputs(
    const float* __restrict__ x,
    const float* __restrict__ wq, const float* __restrict__ wk,
    const float* __restrict__ wv, const float* __restrict__ wo,
    float* __restrict__ xt,
    float* __restrict__ wqt, float* __restrict__ wkt,
    float* __restrict__ wvt, float* __restrict__ wot) {
    const int NX = (B_ * S_ * E_) / 4;   // 2,097,152
    const int NW = (E_ * E_) / 4;        // 262,144
    int i = blockIdx.x * 256 + threadIdx.x;
    if (i < NX) {
        ((float4*)xt)[i] = cvt4(((const float4*)x)[i]);
        return;
    }
    i -= NX;
    const float* s;
    float* d;
    if (i < NW)          { s = wq; d = wqt; }
    else if (i < 2 * NW) { s = wk; d = wkt; i -= NW; }
    else if (i < 3 * NW) { s = wv; d = wvt; i -= 2 * NW; }
    else                 { s = wo; d = wot; i -= 3 * NW; }
    ((float4*)d)[i] = cvt4(((const float4*)s)[i]);
}

// ---------------------------------------------------------------------------
// TF32 tensor-core GEMM: C[M,N] = A[M,K] * W[N,K]^T  (R10 formulation)
// K-chunk = 32, 3-stage cp.async, one wait+sync / 64 MMAs.
// Tile 128x128, 256 threads, warp grid 2x4, warp tile 64x32.
// ---------------------------------------------------------------------------
#define GEMM_SMEM (3 * 16384 * 2)   // 98304 B

template <bool SPLIT>
__global__ __launch_bounds__(256, 2) void gemm_tf32(
    const float* __restrict__ A,
    const float* __restrict__ W0, const float* __restrict__ W1,
    const float* __restrict__ W2,
    float* __restrict__ C0, float* __restrict__ C1, float* __restrict__ C2) {
    const int K = E_;
    extern __shared__ float dsm[];

    const float* W = W0;
    float* C = C0;
    if (blockIdx.z == 1) { W = W1; C = C1; }
    else if (blockIdx.z == 2) { W = W2; C = C2; }

    const int tid = threadIdx.x;
    const int bm = blockIdx.y * 128, bn = blockIdx.x * 128;
    const int wid = tid >> 5, lane = tid & 31;
    const int lr = lane >> 2, lc = lane & 3;
    const int mb = (wid & 1) * 64;
    const int nb = (wid >> 1) * 32;

    const int r0 = tid >> 3;
    const int cg = tid & 7;
    const uint32_t aoff = (uint32_t)(r0 * 128 + ((cg ^ (r0 & 7)) * 16));

    const uint32_t sa = (uint32_t)__cvta_generic_to_shared(dsm);
    const uint32_t sb = sa + 49152u;

    const float* Ap = A + (size_t)(bm + r0) * K + cg * 4;
    const float* Wp = W + (size_t)(bn + r0) * K + cg * 4;

    float acc[4][4][4];
#pragma unroll
    for (int mt = 0; mt < 4; mt++)
#pragma unroll
        for (int nt = 0; nt < 4; nt++)
#pragma unroll
            for (int i = 0; i < 4; i++) acc[mt][nt][i] = 0.f;

    const int NCHUNK = K / 32;  // 32

#pragma unroll
    for (int c = 0; c < 2; c++) {
        const uint32_t st = (uint32_t)c * 16384u;
        const int kc = c * 32;
#pragma unroll
        for (int i = 0; i < 4; i++) {
            cp16(sa + st + aoff + i * 4096u, Ap + (size_t)(i * 32) * K + kc);
            cp16(sb + st + aoff + i * 4096u, Wp + (size_t)(i * 32) * K + kc);
        }
        CP_COMMIT();
    }

#pragma unroll 1
    for (int c = 0; c < NCHUNK; c++) {
        CP_WAIT1();
        __syncthreads();

        if (c + 2 < NCHUNK) {
            const uint32_t st = (uint32_t)((c + 2) % 3) * 16384u;
            const int kc = (c + 2) * 32;
#pragma unroll
            for (int i = 0; i < 4; i++) {
                cp16(sa + st + aoff + i * 4096u, Ap + (size_t)(i * 32) * K + kc);
                cp16(sb + st + aoff + i * 4096u, Wp + (size_t)(i * 32) * K + kc);
            }
        }
        CP_COMMIT();

        const float* Asb = dsm + (c % 3) * 4096;
        const float* Bsb = dsm + 12288 + (c % 3) * 4096;
#pragma unroll
        for (int k0 = 0; k0 < 32; k0 += 8) {
            uint32_t af[4][4], bf[4][2];
#pragma unroll
            for (int mt = 0; mt < 4; mt++) {
                int m = mb + mt * 16 + lr;
                af[mt][0] = __float_as_uint(Asb[SWZ32(m, k0 + lc)]);
                af[mt][1] = __float_as_uint(Asb[SWZ32(m + 8, k0 + lc)]);
                af[mt][2] = __float_as_uint(Asb[SWZ32(m, k0 + 4 + lc)]);
                af[mt][3] = __float_as_uint(Asb[SWZ32(m + 8, k0 + 4 + lc)]);
            }
#pragma unroll
            for (int nt = 0; nt < 4; nt++) {
                int n = nb + nt * 8 + lr;
                bf[nt][0] = __float_as_uint(Bsb[SWZ32(n, k0 + lc)]);
                bf[nt][1] = __float_as_uint(Bsb[SWZ32(n, k0 + 4 + lc)]);
            }
#pragma unroll
            for (int mt = 0; mt < 4; mt++)
#pragma unroll
                for (int nt = 0; nt < 4; nt++)
                    mma_tf32(acc[mt][nt], af[mt], bf[nt]);
        }
    }

#pragma unroll
    for (int mt = 0; mt < 4; mt++) {
#pragma unroll
        for (int nt = 0; nt < 4; nt++) {
            int row = bm + mb + mt * 16 + lr;
            int col = bn + nb + nt * 8 + lc * 2;
#pragma unroll
            for (int half = 0; half < 2; half++) {
                int m = row + half * 8;
                float v0 = acc[mt][nt][half * 2], v1 = acc[mt][nt][half * 2 + 1];
                if (!SPLIT) {
                    *(float2*)(C + (size_t)m * E_ + col) = make_float2(v0, v1);
                } else {
                    int b = m >> 11, sq = m & 2047;
                    int h = col >> 6, d = col & 63;
                    *(float2*)(C + ((((size_t)b * H_ + h) * S_ + sq) * D_ + d)) =
                        make_float2(to_tf32(v0), to_tf32(v1));
                }
            }
        }
    }
}

// ---------------------------------------------------------------------------
// Tensor-core flash attention (tf32 mma, fp32 softmax).
// Heavy-first (LPT) grid. K/V double-buffered via cp.async: tile kt+1's loads
// overlap tile kt's compute. Mask ballots precomputed once -> ONE sync/tile.
// Smem floats: Qs[0,8704) Ks0[8704,13056) Ks1[13056,17408)
//              Vs0[17408,22016) Vs1[22016,26624)   (106496 B)
// ---------------------------------------------------------------------------
#define FA_SMEM (26624 * 4)

__global__ __launch_bounds__(256) void flash_tc(const float* __restrict__ Q,
                                                const float* __restrict__ K,
                                                const float* __restrict__ V,
                                                const int* __restrict__ amask,
                                                float* __restrict__ out) {
    extern __shared__ float smf[];
    float* Qs = smf;                   // 128 x 68
    __shared__ unsigned mkb_all[64];

    const int tid = threadIdx.x;
    const int bh = blockIdx.x;                              // fast dim
    const int qt = (int)(gridDim.y - 1) - (int)blockIdx.y;  // heavy first
    const int b = bh >> 4, h = bh & 15;
    const int qbase = qt * 128;
    const int ntiles = 2 * qt + 2;

    const int lane = tid & 31, wid = tid >> 5;
    const int lr = lane >> 2, lc = lane & 3;
    const int wb = wid * 16;

    const uint32_t sbase = (uint32_t)__cvta_generic_to_shared(smf);

    // K/V prefetch for tile kt into buffer s (8 cp16 per thread)
    auto issue_kv = [&](int kt, int s) {
        const float* Kb = K + ((size_t)bh * S_ + kt * 64) * D_;
        const float* Vb = V + ((size_t)bh * S_ + kt * 64) * D_;
#pragma unroll
        for (int i = 0; i < 4; i++) {
            int e = tid + i * 256;
            int r = e >> 4, c4 = e & 15;
            cp16(sbase + (uint32_t)(8704 + s * 4352 + r * 68 + c4 * 4) * 4,
                 Kb + e * 4);
            cp16(sbase + (uint32_t)(17408 + s * 4608 + r * 72 + c4 * 4) * 4,
                 Vb + e * 4);
        }
    };

    // Prefetch tile 0 first so it overlaps the Q load + mask precompute.
    issue_kv(0, 0);
    CP_COMMIT();

    {   // Q tile load (scaled by 1/8; values already tf32)
        const float* Qb = Q + ((size_t)bh * S_ + qbase) * D_;
        for (int e = tid; e < 2048; e += 256) {
            int r = e >> 4, c4 = e & 15;
            float4 v = ((const float4*)Qb)[e];
            *(float4*)&Qs[r * 68 + c4 * 4] =
                make_float4(v.x * 0.125f, v.y * 0.125f, v.z * 0.125f, v.w * 0.125f);
        }
    }
    // Precompute all mask ballots for this batch (64 words cover S=2048)
#pragma unroll
    for (int i = 0; i < 8; i++) {
        int pos = i * 256 + tid;
        int m = amask[b * S_ + pos];
        unsigned bal = __ballot_sync(0xffffffffu, m != 0);
        if ((tid & 31) == 0) mkb_all[pos >> 5] = bal;
    }

    const int grow0 = qbase + wb + lr;
    const int grow1 = grow0 + 8;

    float oacc[8][4];
#pragma unroll
    for (int nt = 0; nt < 8; nt++)
#pragma unroll
        for (int j = 0; j < 4; j++) oacc[nt][j] = 0.f;

    float mlo = -1e30f, mhi = -1e30f, llo = 0.f, lhi = 0.f;

    for (int kt = 0; kt < ntiles; kt++) {
        CP_WAIT0();
        __syncthreads();   // K/V(kt) visible; prev compute done; Q/mask ready

        // Prefetch next tile into the other buffer; overlaps compute below.
        if (kt + 1 < ntiles) issue_kv(kt + 1, (kt + 1) & 1);
        CP_COMMIT();

        const float* Ksb = smf + 8704 + (kt & 1) * 4352;
        const float* Vsb = smf + 17408 + (kt & 1) * 4608;

        float sacc[8][4];
#pragma unroll
        for (int nt = 0; nt < 8; nt++)
#pragma unroll
            for (int j = 0; j < 4; j++) sacc[nt][j] = 0.f;

#pragma unroll
        for (int ks = 0; ks < 8; ks++) {
            int k0 = ks * 8;
            uint32_t a[4];
            a[0] = __float_as_uint(Qs[(wb + lr) * 68 + k0 + lc]);
            a[1] = __float_as_uint(Qs[(wb + lr + 8) * 68 + k0 + lc]);
            a[2] = __float_as_uint(Qs[(wb + lr) * 68 + k0 + 4 + lc]);
            a[3] = __float_as_uint(Qs[(wb + lr + 8) * 68 + k0 + 4 + lc]);
#pragma unroll
            for (int nt = 0; nt < 8; nt++) {
                uint32_t bb[2];
                bb[0] = __float_as_uint(Ksb[(nt * 8 + lr) * 68 + k0 + lc]);
                bb[1] = __float_as_uint(Ksb[(nt * 8 + lr) * 68 + k0 + 4 + lc]);
                mma_tf32(sacc[nt], a, bb);
            }
        }

        unsigned mb0 = mkb_all[2 * kt], mb1 = mkb_all[2 * kt + 1];
        bool diag = (kt >= 2 * qt);
        bool pad = (mb0 & mb1) != 0xffffffffu;
        if (diag || pad) {
#pragma unroll
            for (int nt = 0; nt < 8; nt++) {
#pragma unroll
                for (int j = 0; j < 4; j++) {
                    int colL = nt * 8 + 2 * lc + (j & 1);
                    int gcol = kt * 64 + colL;
                    int grow = (j < 2) ? grow0 : grow1;
                    unsigned bit = ((colL < 32 ? mb0 : mb1) >> (colL & 31)) & 1u;
                    if (!bit || gcol > grow) sacc[nt][j] = -1e30f;
                }
            }
        }

        float tlo = -1e30f, thi = -1e30f;
#pragma unroll
        for (int nt = 0; nt < 8; nt++) {
            tlo = fmaxf(tlo, fmaxf(sacc[nt][0], sacc[nt][1]));
            thi = fmaxf(thi, fmaxf(sacc[nt][2], sacc[nt][3]));
        }
        tlo = fmaxf(tlo, __shfl_xor_sync(0xffffffffu, tlo, 1));
        tlo = fmaxf(tlo, __shfl_xor_sync(0xffffffffu, tlo, 2));
        thi = fmaxf(thi, __shfl_xor_sync(0xffffffffu, thi, 1));
        thi = fmaxf(thi, __shfl_xor_sync(0xffffffffu, thi, 2));

        float nmlo = fmaxf(mlo, tlo), nmhi = fmaxf(mhi, thi);
        float alo = __expf(mlo - nmlo), ahi = __expf(mhi - nmhi);
        mlo = nmlo; mhi = nmhi;

        float slo = 0.f, shi = 0.f;
#pragma unroll
        for (int nt = 0; nt < 8; nt++) {
            float p0 = to_tf32(__expf(sacc[nt][0] - nmlo));
            float p1 = to_tf32(__expf(sacc[nt][1] - nmlo));
            float p2 = to_tf32(__expf(sacc[nt][2] - nmhi));
            float p3 = to_tf32(__expf(sacc[nt][3] - nmhi));
            sacc[nt][0] = p0; sacc[nt][1] = p1;
            sacc[nt][2] = p2; sacc[nt][3] = p3;
            slo += p0 + p1; shi += p2 + p3;
        }
        slo += __shfl_xor_sync(0xffffffffu, slo, 1);
        slo += __shfl_xor_sync(0xffffffffu, slo, 2);
        shi += __shfl_xor_sync(0xffffffffu, shi, 1);
        shi += __shfl_xor_sync(0xffffffffu, shi, 2);
        llo = llo * alo + slo;
        lhi = lhi * ahi + shi;

#pragma unroll
        for (int nt = 0; nt < 8; nt++) {
            oacc[nt][0] *= alo; oacc[nt][1] *= alo;
            oacc[nt][2] *= ahi; oacc[nt][3] *= ahi;
        }

        const int src0 = (lane & 28) | (lc >> 1);
        const int src1 = src0 + 2;
#pragma unroll
        for (int ks = 0; ks < 8; ks++) {
            float p0 = sacc[ks][0], p1 = sacc[ks][1];
            float p2 = sacc[ks][2], p3 = sacc[ks][3];
            float u0 = __shfl_sync(0xffffffffu, p0, src0);
            float u1 = __shfl_sync(0xffffffffu, p1, src0);
            float u2 = __shfl_sync(0xffffffffu, p2, src0);
            float u3 = __shfl_sync(0xffffffffu, p3, src0);
            float v0 = __shfl_sync(0xffffffffu, p0, src1);
            float v1 = __shfl_sync(0xffffffffu, p1, src1);
            float v2 = __shfl_sync(0xffffffffu, p2, src1);
            float v3 = __shfl_sync(0xffffffffu, p3, src1);
            uint32_t a[4];
            a[0] = __float_as_uint((lc & 1) ? u1 : u0);
            a[1] = __float_as_uint((lc & 1) ? u3 : u2);
            a[2] = __float_as_uint((lc & 1) ? v1 : v0);
            a[3] = __float_as_uint((lc & 1) ? v3 : v2);
#pragma unroll
            for (int nt = 0; nt < 8; nt++) {
                uint32_t bb[2];
                bb[0] = __float_as_uint(Vsb[(ks * 8 + lc) * 72 + nt * 8 + lr]);
                bb[1] = __float_as_uint(Vsb[(ks * 8 + 4 + lc) * 72 + nt * 8 + lr]);
                mma_tf32(oacc[nt], a, bb);
            }
        }
    }

    float il0 = 1.f / llo, il1 = 1.f / lhi;
#pragma unroll
    for (int nt = 0; nt < 8; nt++) {
        int col = nt * 8 + 2 * lc;
        float* p0 = out + ((size_t)b * S_ + grow0) * E_ + h * D_ + col;
        float* p1 = out + ((size_t)b * S_ + grow1) * E_ + h * D_ + col;
        *(float2*)p0 = make_float2(to_tf32(oacc[nt][0] * il0),
                                   to_tf32(oacc[nt][1] * il0));
        *(float2*)p1 = make_float2(to_tf32(oacc[nt][2] * il1),
                                   to_tf32(oacc[nt][3] * il1));
    }
}

// ---------------------------------------------------------------------------
// Launch
// ---------------------------------------------------------------------------
extern "C" void kernel_launch(void* const* d_in, const int* in_sizes, int n_in,
                              void* d_out, int out_size) {
    const float* x     = (const float*)d_in[0];
    const int*   amask = (const int*)d_in[1];
    const float* wq    = (const float*)d_in[2];
    const float* wk    = (const float*)d_in[3];
    const float* wv    = (const float*)d_in[4];
    const float* wo    = (const float*)d_in[5];
    float* out = (float*)d_out;

    float *qp, *kp, *vp, *aop, *xt, *wqt, *wkt, *wvt, *wot;
    cudaGetSymbolAddress((void**)&qp, g_Q);
    cudaGetSymbolAddress((void**)&kp, g_K);
    cudaGetSymbolAddress((void**)&vp, g_V);
    cudaGetSymbolAddress((void**)&aop, g_AO);
    cudaGetSymbolAddress((void**)&xt, g_X);
    cudaGetSymbolAddress((void**)&wqt, g_WQ);
    cudaGetSymbolAddress((void**)&wkt, g_WK);
    cudaGetSymbolAddress((void**)&wvt, g_WV);
    cudaGetSymbolAddress((void**)&wot, g_WO);

    // One-time tf32 rounding of all GEMM inputs
    const int NCVT = (B_ * S_ * E_) / 4 + 4 * (E_ * E_) / 4;  // 3,145,728
    cvt_inputs<<<NCVT / 256, 256>>>(x, wq, wk, wv, wo, xt, wqt, wkt, wvt, wot);

    cudaFuncSetAttribute(gemm_tf32<true>,
                         cudaFuncAttributeMaxDynamicSharedMemorySize, GEMM_SMEM);
    cudaFuncSetAttribute(gemm_tf32<false>,
                         cudaFuncAttributeMaxDynamicSharedMemorySize, GEMM_SMEM);

    // Fused Q/K/V projections
    gemm_tf32<true><<<dim3(E_ / 128, (B_ * S_) / 128, 3), 256, GEMM_SMEM>>>(
        xt, wqt, wkt, wvt, qp, kp, vp);

    // Tensor-core flash attention — heavy-first order + cp.async K/V pipeline
    cudaFuncSetAttribute(flash_tc, cudaFuncAttributeMaxDynamicSharedMemorySize,
                         FA_SMEM);
    flash_tc<<<dim3(B_ * H_, S_ / 128), 256, FA_SMEM>>>(qp, kp, vp, amask, aop);

    // Output projection
    gemm_tf32<false><<<dim3(E_ / 128, (B_ * S_) / 128, 1), 256, GEMM_SMEM>>>(
        aop, wot, wot, wot, out, out, out);
}